// round 15
// baseline (speedup 1.0000x reference)
#include <cuda_runtime.h>
#include <cuda_fp16.h>
#include <cstdint>

#define BB   4
#define TT   2048
#define EMB  1024
#define NH   16
#define DFF  4096
#define MR   (BB*TT)   // 8192 rows

#define NEG_INF (__int_as_float(0xff800000))

// ---------------- scratch (static device globals; no allocation) ----------------
__device__ __half g_xh  [(size_t)MR * EMB];
__device__ __half g_qkvh[(size_t)MR * 3 * EMB];
__device__ __half g_atth[(size_t)MR * EMB];
__device__ float  g_res1[(size_t)MR * EMB];
__device__ float  g_x1f [(size_t)MR * EMB];
__device__ __half g_x1h [(size_t)MR * EMB];
__device__ __half g_ffh [(size_t)MR * DFF];
__device__ float  g_res2[(size_t)MR * EMB];
__device__ __half g_watT[(size_t)3*EMB * EMB];
__device__ __half g_wprT[(size_t)EMB * EMB];
__device__ __half g_wf1T[(size_t)DFF * EMB];
__device__ __half g_wf2T[(size_t)EMB * DFF];

// ================= helpers =================
static __device__ __forceinline__ uint32_t s2u(const void* p) {
    uint32_t a;
    asm("{ .reg .u64 t; cvta.to.shared.u64 t, %1; cvt.u32.u64 %0, t; }" : "=r"(a) : "l"(p));
    return a;
}
static __device__ __forceinline__ void cpa16(uint32_t s, const void* g) {
    asm volatile("cp.async.cg.shared.global [%0], [%1], 16;" :: "r"(s), "l"(g));
}
#define CP_COMMIT() asm volatile("cp.async.commit_group;" ::: "memory")
#define CP_WAIT(n)  asm volatile("cp.async.wait_group %0;" :: "n"(n) : "memory")

static __device__ __forceinline__ void ldm_x4(uint32_t* r, uint32_t a) {
    asm volatile("ldmatrix.sync.aligned.m8n8.x4.shared.b16 {%0,%1,%2,%3}, [%4];"
        : "=r"(r[0]), "=r"(r[1]), "=r"(r[2]), "=r"(r[3]) : "r"(a));
}
static __device__ __forceinline__ void ldm_x2(uint32_t* r, uint32_t a) {
    asm volatile("ldmatrix.sync.aligned.m8n8.x2.shared.b16 {%0,%1}, [%2];"
        : "=r"(r[0]), "=r"(r[1]) : "r"(a));
}
static __device__ __forceinline__ void ldm_x2_t(uint32_t* r, uint32_t a) {
    asm volatile("ldmatrix.sync.aligned.m8n8.x2.trans.shared.b16 {%0,%1}, [%2];"
        : "=r"(r[0]), "=r"(r[1]) : "r"(a));
}
// D += A@B  (m16n8k16, fp16 inputs, fp32 accum)
static __device__ __forceinline__ void mma_f16(float* d, const uint32_t* a, const uint32_t* b) {
    asm volatile(
        "mma.sync.aligned.m16n8k16.row.col.f32.f16.f16.f32 "
        "{%0,%1,%2,%3}, {%4,%5,%6,%7}, {%8,%9}, {%0,%1,%2,%3};"
        : "+f"(d[0]), "+f"(d[1]), "+f"(d[2]), "+f"(d[3])
        : "r"(a[0]), "r"(a[1]), "r"(a[2]), "r"(a[3]), "r"(b[0]), "r"(b[1]));
}
static __device__ __forceinline__ uint32_t pack_h2(float a, float b) {
    __half2 h = __floats2half2_rn(a, b);
    return *(uint32_t*)&h;
}

// ================= x -> half =================
__global__ __launch_bounds__(256)
void cvt_half(const float4* __restrict__ in, uint2* __restrict__ out)
{
    size_t i = (size_t)blockIdx.x * 256 + threadIdx.x;
    float4 v = in[i];
    out[i] = make_uint2(pack_h2(v.x, v.y), pack_h2(v.z, v.w));
}

// ================= weight transpose -> half =================
__global__ __launch_bounds__(256)
void transpose_cvt(const float* __restrict__ in, __half* __restrict__ out, int K, int N)
{
    __shared__ float t[32][33];
    const int n0 = blockIdx.x * 32, k0 = blockIdx.y * 32;
    const int tx = threadIdx.x, ty = threadIdx.y;
    #pragma unroll
    for (int i = 0; i < 32; i += 8)
        t[ty + i][tx] = in[(size_t)(k0 + ty + i) * N + n0 + tx];
    __syncthreads();
    #pragma unroll
    for (int i = 0; i < 32; i += 8)
        out[(size_t)(n0 + ty + i) * K + k0 + tx] = __float2half_rn(t[tx][ty + i]);
}

// ================= fp16 mma GEMM (R9 config: BK=32, 3-stage, occ 2) =================
// block 128x128, 256 thr, warp grid 2(m) x 4(n), warp tile 64x32.
#define GPH     40                    // smem pitch (halves) = 80 B
#define GTILEH  (128*GPH)             // halves per stage per operand
#define GSMEM   (6*GTILEH*2)          // bytes: 3 stages x (A,B) = 60 KB

template<bool RELU, bool RESID, bool HOUT>
__global__ __launch_bounds__(256, 2)
void gemm_mma(const __half* __restrict__ A, const __half* __restrict__ Bt,
              const float* __restrict__ bias, const float* __restrict__ Rm,
              float* __restrict__ Cf, __half* __restrict__ Ch, int N, int K)
{
    extern __shared__ __half sh[];
    __half* Asm = sh;                 // [3][128][GPH]
    __half* Bsm = sh + 3*GTILEH;

    const int tid = threadIdx.x;
    const int wid = tid >> 5, lane = tid & 31;
    const int wm = wid >> 2, wn = wid & 3;
    const int g = lane >> 2, q = lane & 3;
    const int Lt = lane >> 3, Lr = lane & 7;
    const int mBase = blockIdx.y << 7, nBase = blockIdx.x << 7;
    const int lrow = tid >> 1, lcH = (tid & 1) << 4;   // 2 threads/row

    const __half* ap = A  + (size_t)(mBase + lrow) * K + lcH;
    const __half* bp = Bt + (size_t)(nBase + lrow) * K + lcH;
    const uint32_t sAld = s2u(Asm) + (uint32_t)(lrow*GPH + lcH) * 2;
    const uint32_t sBld = s2u(Bsm) + (uint32_t)(lrow*GPH + lcH) * 2;

    // ldmatrix lane bases
    uint32_t aAddr[4], bAddr[4];
    #pragma unroll
    for (int mt = 0; mt < 4; mt++) {
        const int row = wm*64 + mt*16 + (Lt & 1)*8 + Lr;
        aAddr[mt] = s2u(Asm) + (uint32_t)((row*GPH + (Lt >> 1)*8) * 2);
    }
    #pragma unroll
    for (int nt = 0; nt < 4; nt++) {
        const int row = wn*32 + nt*8 + Lr;
        bAddr[nt] = s2u(Bsm) + (uint32_t)((row*GPH + (Lt & 1)*8) * 2);
    }

    float acc[16][4];
    #pragma unroll
    for (int i = 0; i < 16; i++)
        #pragma unroll
        for (int j = 0; j < 4; j++) acc[i][j] = 0.f;

    const int nT = K >> 5;

    #pragma unroll
    for (int s = 0; s < 2; s++) {
        const uint32_t so = (uint32_t)(s * GTILEH) * 2;
        const size_t kof = (size_t)s * 32;
        cpa16(sAld + so,      ap + kof);
        cpa16(sAld + so + 16, ap + kof + 8);
        cpa16(sBld + so,      bp + kof);
        cpa16(sBld + so + 16, bp + kof + 8);
        CP_COMMIT();
    }

    #pragma unroll 1
    for (int t = 0; t < nT; ++t) {
        if (t + 1 < nT) { CP_WAIT(1); } else { CP_WAIT(0); }
        __syncthreads();

        if (t + 2 < nT) {
            const int st = (t + 2) % 3;
            const uint32_t so = (uint32_t)(st * GTILEH) * 2;
            const size_t kof = (size_t)(t + 2) * 32;
            cpa16(sAld + so,      ap + kof);
            cpa16(sAld + so + 16, ap + kof + 8);
            cpa16(sBld + so,      bp + kof);
            cpa16(sBld + so + 16, bp + kof + 8);
            CP_COMMIT();
        }

        const uint32_t so = (uint32_t)((t % 3) * GTILEH) * 2;
        #pragma unroll
        for (int ks = 0; ks < 2; ks++) {          // two k16 steps per BK=32
            const uint32_t kb = (uint32_t)(ks * 32);   // 16 halves = 32 B
            uint32_t af[4][4], bf[4][2];
            #pragma unroll
            for (int mt = 0; mt < 4; mt++) ldm_x4(af[mt], aAddr[mt] + so + kb);
            #pragma unroll
            for (int nt = 0; nt < 4; nt++) ldm_x2(bf[nt], bAddr[nt] + so + kb);
            #pragma unroll
            for (int mt = 0; mt < 4; mt++)
                #pragma unroll
                for (int nt = 0; nt < 4; nt++)
                    mma_f16(acc[mt*4 + nt], af[mt], bf[nt]);
        }
    }

    // epilogue
    #pragma unroll
    for (int mt = 0; mt < 4; mt++) {
        const int row0 = mBase + wm*64 + mt*16 + g;
        #pragma unroll
        for (int nt = 0; nt < 4; nt++) {
            const int col = nBase + wn*32 + nt*8 + 2*q;
            const float* a4 = acc[mt*4 + nt];
            float2 bv = *(const float2*)(bias + col);
            float o0 = a4[0] + bv.x, o1 = a4[1] + bv.y;
            float o2 = a4[2] + bv.x, o3 = a4[3] + bv.y;
            if (RESID) {
                float2 u = *(const float2*)(Rm + (size_t)row0*N + col);
                float2 v = *(const float2*)(Rm + (size_t)(row0+8)*N + col);
                o0 += u.x; o1 += u.y; o2 += v.x; o3 += v.y;
            }
            if (RELU) {
                o0 = fmaxf(o0, 0.f); o1 = fmaxf(o1, 0.f);
                o2 = fmaxf(o2, 0.f); o3 = fmaxf(o3, 0.f);
            }
            if (HOUT) {
                *(uint32_t*)(Ch + (size_t)row0*N + col)     = pack_h2(o0, o1);
                *(uint32_t*)(Ch + (size_t)(row0+8)*N + col) = pack_h2(o2, o3);
            } else {
                *(float2*)(Cf + (size_t)row0*N + col)     = make_float2(o0, o1);
                *(float2*)(Cf + (size_t)(row0+8)*N + col) = make_float2(o2, o3);
            }
        }
    }
}

// ---------------- Flash attention (fp16 mma, causal, 128q x 64kv) ----------------
// 8 warps (256 thr), warp owns 16 q-rows; K/V shared by all 8 warps -> half traffic.
#define KP 72                           // pitch (halves) = 144 B
#define ATT_SMEM ((2*64*KP + 2*64*KP + 8*16*KP + 8*16*KP) * 2)

__global__ __launch_bounds__(256, 2)
void attn_kernel(const __half* __restrict__ qkv, __half* __restrict__ out)
{
    extern __shared__ __half sa[];
    __half* Ksm = sa;                    // [2][64][KP]
    __half* Vsm = Ksm + 2*64*KP;         // [2][64][KP]
    __half* Psm = Vsm + 2*64*KP;         // [8][16][KP]
    __half* Qsm = Psm + 8*16*KP;         // [8][16][KP]

    const int tid = threadIdx.x;
    const int w = tid >> 5, lane = tid & 31;
    const int g = lane >> 2, q = lane & 3;
    const int Lt = lane >> 3, Lr = lane & 7;
    const int qi = (gridDim.x - 1) - blockIdx.x;   // longest first
    const int h = blockIdx.y, b = blockIdx.z;
    const int qBase = qi * 128;
    const size_t bT = (size_t)b * TT;

    __half* Pw = Psm + w*16*KP;
    __half* Qw = Qsm + w*16*KP;

    // load Q tile (16 rows x 64 halves per warp)
    {
        const __half* qg = qkv + (bT + qBase + w*16) * 3072 + h*64;
        #pragma unroll
        for (int i = 0; i < 4; i++) {
            int f = lane + i*32;
            int r = f >> 3, c8 = (f & 7) << 3;
            *(uint4*)&Qw[r*KP + c8] = *(const uint4*)(qg + (size_t)r*3072 + c8);
        }
    }
    __syncwarp();

    float m0 = NEG_INF, m1 = NEG_INF, l0 = 0.f, l1 = 0.f;
    float accO[8][4];
    #pragma unroll
    for (int i = 0; i < 8; i++)
        #pragma unroll
        for (int j = 0; j < 4; j++) accO[i][j] = 0.f;

    const int nT = 2*qi + 2;            // kv tiles of 64
    const uint32_t skb = s2u(Ksm), svb = s2u(Vsm);
    const uint32_t lmq = s2u(Qw) + (uint32_t)(((((Lt & 1)*8) + Lr)*KP + (Lt >> 1)*8) * 2);
    const uint32_t lmp = s2u(Pw) + (uint32_t)(((((Lt & 1)*8) + Lr)*KP + (Lt >> 1)*8) * 2);
    const uint32_t lmk = skb + (uint32_t)((Lr*KP + (Lt & 1)*8) * 2);   // K frag base
    const uint32_t lmv = svb + (uint32_t)((((Lt & 1)*8 + Lr)*KP) * 2); // V frag base (trans)

    // prologue: kv tile 0 -> stage 0 (256 threads, 64 rows x 8 chunks)
    {
        const __half* kg = qkv + bT * 3072 + EMB + h*64;
        #pragma unroll
        for (int i = 0; i < 2; i++) {
            int f = tid + i*256;
            int r = f >> 3, c8 = (f & 7) << 3;
            cpa16(skb + (uint32_t)((r*KP + c8)*2), kg + (size_t)r*3072 + c8);
            cpa16(svb + (uint32_t)((r*KP + c8)*2), kg + (size_t)r*3072 + EMB + c8);
        }
        CP_COMMIT();
    }

    #pragma unroll 1
    for (int j = 0; j < nT; ++j) {
        if (j + 1 < nT) {
            const int st = (j + 1) & 1;
            const __half* kg = qkv + (bT + (size_t)(j+1)*64) * 3072 + EMB + h*64;
            #pragma unroll
            for (int i = 0; i < 2; i++) {
                int f = tid + i*256;
                int r = f >> 3, c8 = (f & 7) << 3;
                cpa16(skb + (uint32_t)(((st*64 + r)*KP + c8)*2), kg + (size_t)r*3072 + c8);
                cpa16(svb + (uint32_t)(((st*64 + r)*KP + c8)*2), kg + (size_t)r*3072 + EMB + c8);
            }
            CP_COMMIT();
            CP_WAIT(1);
        } else {
            CP_WAIT(0);
        }
        __syncthreads();

        const int jb = j * 64;
        const bool active = (jb <= qBase + w*16 + 15);   // tile intersects this warp's rows
        if (active) {
            const uint32_t kst = (uint32_t)((j & 1) * 64 * KP * 2);

            // ---- S = Q @ K^T : 8 n-tiles, 4 k16 steps ----
            float sacc[8][4];
            #pragma unroll
            for (int i = 0; i < 8; i++)
                #pragma unroll
                for (int jj = 0; jj < 4; jj++) sacc[i][jj] = 0.f;

            #pragma unroll
            for (int ks = 0; ks < 4; ks++) {
                const uint32_t kb = (uint32_t)(ks * 32);   // 16 halves
                uint32_t aq[4];
                ldm_x4(aq, lmq + kb);
                uint32_t bf[8][2];
                #pragma unroll
                for (int nt = 0; nt < 8; nt++)
                    ldm_x2(bf[nt], lmk + kst + (uint32_t)(nt*8*KP*2) + kb);
                #pragma unroll
                for (int nt = 0; nt < 8; nt++)
                    mma_f16(sacc[nt], aq, bf[nt]);
            }

            // scale + causal mask (tiles overlapping this warp's diagonal)
            const int r0 = qBase + w*16 + g;
            const bool maskT = (jb + 63 > r0);
            #pragma unroll
            for (int nt = 0; nt < 8; nt++) {
                sacc[nt][0] *= 0.125f; sacc[nt][1] *= 0.125f;
                sacc[nt][2] *= 0.125f; sacc[nt][3] *= 0.125f;
                if (maskT) {
                    const int c0 = jb + nt*8 + 2*q;
                    if (c0     > r0    ) sacc[nt][0] = NEG_INF;
                    if (c0 + 1 > r0    ) sacc[nt][1] = NEG_INF;
                    if (c0     > r0 + 8) sacc[nt][2] = NEG_INF;
                    if (c0 + 1 > r0 + 8) sacc[nt][3] = NEG_INF;
                }
            }

            // ---- online softmax in registers ----
            float ml0 = NEG_INF, ml1 = NEG_INF;
            #pragma unroll
            for (int nt = 0; nt < 8; nt++) {
                ml0 = fmaxf(ml0, fmaxf(sacc[nt][0], sacc[nt][1]));
                ml1 = fmaxf(ml1, fmaxf(sacc[nt][2], sacc[nt][3]));
            }
            ml0 = fmaxf(ml0, __shfl_xor_sync(0xffffffffu, ml0, 1));
            ml0 = fmaxf(ml0, __shfl_xor_sync(0xffffffffu, ml0, 2));
            ml1 = fmaxf(ml1, __shfl_xor_sync(0xffffffffu, ml1, 1));
            ml1 = fmaxf(ml1, __shfl_xor_sync(0xffffffffu, ml1, 2));
            const float mn0 = fmaxf(m0, ml0);
            const float mn1 = fmaxf(m1, ml1);
            const float a0 = __expf(m0 - mn0);
            const float a1 = __expf(m1 - mn1);
            float s0 = 0.f, s1 = 0.f;
            #pragma unroll
            for (int nt = 0; nt < 8; nt++) {
                sacc[nt][0] = __expf(sacc[nt][0] - mn0);
                sacc[nt][1] = __expf(sacc[nt][1] - mn0);
                sacc[nt][2] = __expf(sacc[nt][2] - mn1);
                sacc[nt][3] = __expf(sacc[nt][3] - mn1);
                s0 += sacc[nt][0] + sacc[nt][1];
                s1 += sacc[nt][2] + sacc[nt][3];
            }
            s0 += __shfl_xor_sync(0xffffffffu, s0, 1);
            s0 += __shfl_xor_sync(0xffffffffu, s0, 2);
            s1 += __shfl_xor_sync(0xffffffffu, s1, 1);
            s1 += __shfl_xor_sync(0xffffffffu, s1, 2);
            m0 = mn0; m1 = mn1;
            l0 = l0 * a0 + s0;
            l1 = l1 * a1 + s1;
            #pragma unroll
            for (int dt = 0; dt < 8; dt++) {
                accO[dt][0] *= a0; accO[dt][1] *= a0;
                accO[dt][2] *= a1; accO[dt][3] *= a1;
            }

            // ---- P (half) -> warp-private smem ----
            #pragma unroll
            for (int nt = 0; nt < 8; nt++) {
                const int c = nt*8 + 2*q;
                *(uint32_t*)&Pw[(g    )*KP + c] = pack_h2(sacc[nt][0], sacc[nt][1]);
                *(uint32_t*)&Pw[(g + 8)*KP + c] = pack_h2(sacc[nt][2], sacc[nt][3]);
            }
            __syncwarp();

            // ---- O += P @ V : A = P (ldm x4), B = V (ldm x2 trans) ----
            #pragma unroll
            for (int ks = 0; ks < 4; ks++) {
                const uint32_t kb = (uint32_t)(ks * 32);
                uint32_t af[4];
                ldm_x4(af, lmp + kb);
                const uint32_t vrow = lmv + kst + (uint32_t)(ks*16*KP*2);
                uint32_t bf[8][2];
                #pragma unroll
                for (int dt = 0; dt < 8; dt++)
                    ldm_x2_t(bf[dt], vrow + (uint32_t)(dt*8*2));
                #pragma unroll
                for (int dt = 0; dt < 8; dt++)
                    mma_f16(accO[dt], af, bf[dt]);
            }
            __syncwarp();
        }
        __syncthreads();
    }

    // ---- finalize: divide by l, write half out [b,t,e] ----
    const float inv0 = 1.f / l0;
    const float inv1 = 1.f / l1;
    const size_t row0 = bT + qBase + w*16 + g;
    #pragma unroll
    for (int dt = 0; dt < 8; dt++) {
        const int c = h*64 + dt*8 + 2*q;
        *(uint32_t*)(out + row0*EMB + c)       = pack_h2(accO[dt][0]*inv0, accO[dt][1]*inv0);
        *(uint32_t*)(out + (row0 + 8)*EMB + c) = pack_h2(accO[dt][2]*inv1, accO[dt][3]*inv1);
    }
}

// ---------------- LayerNorm over last dim (1024) ----------------
__global__ __launch_bounds__(256)
void ln_kernel(const float* __restrict__ in, const float* __restrict__ g,
               const float* __restrict__ bb, float* __restrict__ out,
               __half* __restrict__ outh)
{
    const int row = blockIdx.x, tid = threadIdx.x;
    const float* rp = in + (size_t)row * EMB;
    float4 v = *(const float4*)(rp + tid*4);
    float s  = v.x + v.y + v.z + v.w;
    float sq = v.x*v.x + v.y*v.y + v.z*v.z + v.w*v.w;
    #pragma unroll
    for (int o = 16; o > 0; o >>= 1) {
        s  += __shfl_xor_sync(0xffffffffu, s,  o);
        sq += __shfl_xor_sync(0xffffffffu, sq, o);
    }
    __shared__ float ws[8], wq[8], stat[2];
    const int w = tid >> 5;
    if ((tid & 31) == 0) { ws[w] = s; wq[w] = sq; }
    __syncthreads();
    if (tid == 0) {
        float ts = 0.f, tq = 0.f;
        #pragma unroll
        for (int i = 0; i < 8; i++) { ts += ws[i]; tq += wq[i]; }
        float mean = ts * (1.f/EMB);
        float var  = tq * (1.f/EMB) - mean*mean;
        stat[0] = mean;
        stat[1] = rsqrtf(var + 1e-5f);
    }
    __syncthreads();
    const float mean = stat[0], rs = stat[1];
    float4 gv = *(const float4*)(g  + tid*4);
    float4 bv = *(const float4*)(bb + tid*4);
    float4 o;
    o.x = (v.x - mean)*rs*gv.x + bv.x;
    o.y = (v.y - mean)*rs*gv.y + bv.y;
    o.z = (v.z - mean)*rs*gv.z + bv.z;
    o.w = (v.w - mean)*rs*gv.w + bv.w;
    *(float4*)(out + (size_t)row*EMB + tid*4) = o;
    if (outh) {
        *(uint2*)(outh + (size_t)row*EMB + tid*4) =
            make_uint2(pack_h2(o.x, o.y), pack_h2(o.z, o.w));
    }
}

// ---------------- launch ----------------
extern "C" void kernel_launch(void* const* d_in, const int* in_sizes, int n_in,
                              void* d_out, int out_size)
{
    const float* x   = (const float*)d_in[0];
    const float* wat = (const float*)d_in[1];
    const float* bat = (const float*)d_in[2];
    const float* wpr = (const float*)d_in[3];
    const float* bpr = (const float*)d_in[4];
    const float* l1g = (const float*)d_in[5];
    const float* l1b = (const float*)d_in[6];
    const float* wf1 = (const float*)d_in[7];
    const float* bf1 = (const float*)d_in[8];
    const float* wf2 = (const float*)d_in[9];
    const float* bf2 = (const float*)d_in[10];
    const float* l2g = (const float*)d_in[11];
    const float* l2b = (const float*)d_in[12];

    static __half *xh = nullptr, *qkvh, *atth, *x1h, *ffh, *watT, *wprT, *wf1T, *wf2T;
    static float *res1, *x1f, *res2;
    if (!xh) {
        cudaGetSymbolAddress((void**)&xh,   g_xh);
        cudaGetSymbolAddress((void**)&qkvh, g_qkvh);
        cudaGetSymbolAddress((void**)&atth, g_atth);
        cudaGetSymbolAddress((void**)&res1, g_res1);
        cudaGetSymbolAddress((void**)&x1f,  g_x1f);
        cudaGetSymbolAddress((void**)&x1h,  g_x1h);
        cudaGetSymbolAddress((void**)&ffh,  g_ffh);
        cudaGetSymbolAddress((void**)&res2, g_res2);
        cudaGetSymbolAddress((void**)&watT, g_watT);
        cudaGetSymbolAddress((void**)&wprT, g_wprT);
        cudaGetSymbolAddress((void**)&wf1T, g_wf1T);
        cudaGetSymbolAddress((void**)&wf2T, g_wf2T);
        cudaFuncSetAttribute(attn_kernel, cudaFuncAttributeMaxDynamicSharedMemorySize, ATT_SMEM);
        cudaFuncSetAttribute(gemm_mma<false,false,true>, cudaFuncAttributeMaxDynamicSharedMemorySize, GSMEM);
        cudaFuncSetAttribute(gemm_mma<false,true,false>, cudaFuncAttributeMaxDynamicSharedMemorySize, GSMEM);
        cudaFuncSetAttribute(gemm_mma<true,false,true>,  cudaFuncAttributeMaxDynamicSharedMemorySize, GSMEM);
    }

    // x -> half; weights transpose -> half
    cvt_half<<<MR*EMB/1024, 256>>>((const float4*)x, (uint2*)xh);
    transpose_cvt<<<dim3(3*EMB/32, EMB/32), dim3(32,8)>>>(wat, watT, EMB, 3*EMB);
    transpose_cvt<<<dim3(EMB/32,   EMB/32), dim3(32,8)>>>(wpr, wprT, EMB, EMB);
    transpose_cvt<<<dim3(DFF/32,   EMB/32), dim3(32,8)>>>(wf1, wf1T, EMB, DFF);
    transpose_cvt<<<dim3(EMB/32,   DFF/32), dim3(32,8)>>>(wf2, wf2T, DFF, EMB);

    // 1. QKV projection -> half
    gemm_mma<false,false,true><<<dim3(3*EMB/128, MR/128), 256, GSMEM>>>(xh, watT, bat, nullptr, nullptr, qkvh, 3*EMB, EMB);
    // 2. causal flash attention -> half (128 q-rows per block)
    attn_kernel<<<dim3(TT/128, NH, BB), 256, ATT_SMEM>>>(qkvh, atth);
    // 3. output proj + residual(x) -> fp32
    gemm_mma<false,true,false><<<dim3(EMB/128, MR/128), 256, GSMEM>>>(atth, wprT, bpr, x, res1, nullptr, EMB, EMB);
    // 4. LN1 -> x1f (fp32) + x1h (half)
    ln_kernel<<<MR, 256>>>(res1, l1g, l1b, x1f, x1h);
    // 5. FF1 + ReLU -> half
    gemm_mma<true,false,true><<<dim3(DFF/128, MR/128), 256, GSMEM>>>(x1h, wf1T, bf1, nullptr, nullptr, ffh, DFF, EMB);
    // 6. FF2 + residual(x1f) -> fp32
    gemm_mma<false,true,false><<<dim3(EMB/128, MR/128), 256, GSMEM>>>(ffh, wf2T, bf2, x1f, res2, nullptr, EMB, DFF);
    // 7. LN2 -> out
    ln_kernel<<<MR, 256>>>(res2, l2g, l2b, (float*)d_out, nullptr);
}

// round 16
// speedup vs baseline: 1.0347x; 1.0347x over previous
#include <cuda_runtime.h>
#include <cuda_fp16.h>
#include <cstdint>

#define BB   4
#define TT   2048
#define EMB  1024
#define NH   16
#define DFF  4096
#define MR   (BB*TT)   // 8192 rows

#define NEG_INF (__int_as_float(0xff800000))

// ---------------- scratch (static device globals; no allocation) ----------------
__device__ __half g_xh  [(size_t)MR * EMB];
__device__ __half g_qkvh[(size_t)MR * 3 * EMB];
__device__ __half g_atth[(size_t)MR * EMB];
__device__ float  g_res1[(size_t)MR * EMB];
__device__ float  g_x1f [(size_t)MR * EMB];
__device__ __half g_x1h [(size_t)MR * EMB];
__device__ __half g_ffh [(size_t)MR * DFF];
__device__ float  g_res2[(size_t)MR * EMB];
__device__ __half g_watT[(size_t)3*EMB * EMB];
__device__ __half g_wprT[(size_t)EMB * EMB];
__device__ __half g_wf1T[(size_t)DFF * EMB];
__device__ __half g_wf2T[(size_t)EMB * DFF];

// ================= helpers =================
static __device__ __forceinline__ uint32_t s2u(const void* p) {
    uint32_t a;
    asm("{ .reg .u64 t; cvta.to.shared.u64 t, %1; cvt.u32.u64 %0, t; }" : "=r"(a) : "l"(p));
    return a;
}
static __device__ __forceinline__ void cpa16(uint32_t s, const void* g) {
    asm volatile("cp.async.cg.shared.global [%0], [%1], 16;" :: "r"(s), "l"(g));
}
#define CP_COMMIT() asm volatile("cp.async.commit_group;" ::: "memory")
#define CP_WAIT(n)  asm volatile("cp.async.wait_group %0;" :: "n"(n) : "memory")

static __device__ __forceinline__ void ldm_x4(uint32_t* r, uint32_t a) {
    asm volatile("ldmatrix.sync.aligned.m8n8.x4.shared.b16 {%0,%1,%2,%3}, [%4];"
        : "=r"(r[0]), "=r"(r[1]), "=r"(r[2]), "=r"(r[3]) : "r"(a));
}
static __device__ __forceinline__ void ldm_x2(uint32_t* r, uint32_t a) {
    asm volatile("ldmatrix.sync.aligned.m8n8.x2.shared.b16 {%0,%1}, [%2];"
        : "=r"(r[0]), "=r"(r[1]) : "r"(a));
}
static __device__ __forceinline__ void ldm_x2_t(uint32_t* r, uint32_t a) {
    asm volatile("ldmatrix.sync.aligned.m8n8.x2.trans.shared.b16 {%0,%1}, [%2];"
        : "=r"(r[0]), "=r"(r[1]) : "r"(a));
}
// D += A@B  (m16n8k16, fp16 inputs, fp32 accum)
static __device__ __forceinline__ void mma_f16(float* d, const uint32_t* a, const uint32_t* b) {
    asm volatile(
        "mma.sync.aligned.m16n8k16.row.col.f32.f16.f16.f32 "
        "{%0,%1,%2,%3}, {%4,%5,%6,%7}, {%8,%9}, {%0,%1,%2,%3};"
        : "+f"(d[0]), "+f"(d[1]), "+f"(d[2]), "+f"(d[3])
        : "r"(a[0]), "r"(a[1]), "r"(a[2]), "r"(a[3]), "r"(b[0]), "r"(b[1]));
}
static __device__ __forceinline__ uint32_t pack_h2(float a, float b) {
    __half2 h = __floats2half2_rn(a, b);
    return *(uint32_t*)&h;
}

// ================= x -> half =================
__global__ __launch_bounds__(256)
void cvt_half(const float4* __restrict__ in, uint2* __restrict__ out)
{
    size_t i = (size_t)blockIdx.x * 256 + threadIdx.x;
    float4 v = in[i];
    out[i] = make_uint2(pack_h2(v.x, v.y), pack_h2(v.z, v.w));
}

// ================= weight transpose -> half =================
__global__ __launch_bounds__(256)
void transpose_cvt(const float* __restrict__ in, __half* __restrict__ out, int K, int N)
{
    __shared__ float t[32][33];
    const int n0 = blockIdx.x * 32, k0 = blockIdx.y * 32;
    const int tx = threadIdx.x, ty = threadIdx.y;
    #pragma unroll
    for (int i = 0; i < 32; i += 8)
        t[ty + i][tx] = in[(size_t)(k0 + ty + i) * N + n0 + tx];
    __syncthreads();
    #pragma unroll
    for (int i = 0; i < 32; i += 8)
        out[(size_t)(n0 + ty + i) * K + k0 + tx] = __float2half_rn(t[tx][ty + i]);
}

// ================= fp16 mma GEMM (R9 config: BK=32, 3-stage, occ 2) =================
// block 128x128, 256 thr, warp grid 2(m) x 4(n), warp tile 64x32.
#define GPH     40                    // smem pitch (halves) = 80 B
#define GTILEH  (128*GPH)             // halves per stage per operand
#define GSMEM   (6*GTILEH*2)          // bytes: 3 stages x (A,B) = 60 KB

template<bool RELU, bool RESID, bool HOUT>
__global__ __launch_bounds__(256, 2)
void gemm_mma(const __half* __restrict__ A, const __half* __restrict__ Bt,
              const float* __restrict__ bias, const float* __restrict__ Rm,
              float* __restrict__ Cf, __half* __restrict__ Ch, int N, int K)
{
    extern __shared__ __half sh[];
    __half* Asm = sh;                 // [3][128][GPH]
    __half* Bsm = sh + 3*GTILEH;

    const int tid = threadIdx.x;
    const int wid = tid >> 5, lane = tid & 31;
    const int wm = wid >> 2, wn = wid & 3;
    const int g = lane >> 2, q = lane & 3;
    const int Lt = lane >> 3, Lr = lane & 7;
    const int mBase = blockIdx.y << 7, nBase = blockIdx.x << 7;
    const int lrow = tid >> 1, lcH = (tid & 1) << 4;   // 2 threads/row

    const __half* ap = A  + (size_t)(mBase + lrow) * K + lcH;
    const __half* bp = Bt + (size_t)(nBase + lrow) * K + lcH;
    const uint32_t sAld = s2u(Asm) + (uint32_t)(lrow*GPH + lcH) * 2;
    const uint32_t sBld = s2u(Bsm) + (uint32_t)(lrow*GPH + lcH) * 2;

    // ldmatrix lane bases
    uint32_t aAddr[4], bAddr[4];
    #pragma unroll
    for (int mt = 0; mt < 4; mt++) {
        const int row = wm*64 + mt*16 + (Lt & 1)*8 + Lr;
        aAddr[mt] = s2u(Asm) + (uint32_t)((row*GPH + (Lt >> 1)*8) * 2);
    }
    #pragma unroll
    for (int nt = 0; nt < 4; nt++) {
        const int row = wn*32 + nt*8 + Lr;
        bAddr[nt] = s2u(Bsm) + (uint32_t)((row*GPH + (Lt & 1)*8) * 2);
    }

    float acc[16][4];
    #pragma unroll
    for (int i = 0; i < 16; i++)
        #pragma unroll
        for (int j = 0; j < 4; j++) acc[i][j] = 0.f;

    const int nT = K >> 5;

    #pragma unroll
    for (int s = 0; s < 2; s++) {
        const uint32_t so = (uint32_t)(s * GTILEH) * 2;
        const size_t kof = (size_t)s * 32;
        cpa16(sAld + so,      ap + kof);
        cpa16(sAld + so + 16, ap + kof + 8);
        cpa16(sBld + so,      bp + kof);
        cpa16(sBld + so + 16, bp + kof + 8);
        CP_COMMIT();
    }

    #pragma unroll 1
    for (int t = 0; t < nT; ++t) {
        if (t + 1 < nT) { CP_WAIT(1); } else { CP_WAIT(0); }
        __syncthreads();

        if (t + 2 < nT) {
            const int st = (t + 2) % 3;
            const uint32_t so = (uint32_t)(st * GTILEH) * 2;
            const size_t kof = (size_t)(t + 2) * 32;
            cpa16(sAld + so,      ap + kof);
            cpa16(sAld + so + 16, ap + kof + 8);
            cpa16(sBld + so,      bp + kof);
            cpa16(sBld + so + 16, bp + kof + 8);
            CP_COMMIT();
        }

        const uint32_t so = (uint32_t)((t % 3) * GTILEH) * 2;
        #pragma unroll
        for (int ks = 0; ks < 2; ks++) {          // two k16 steps per BK=32
            const uint32_t kb = (uint32_t)(ks * 32);   // 16 halves = 32 B
            uint32_t af[4][4], bf[4][2];
            #pragma unroll
            for (int mt = 0; mt < 4; mt++) ldm_x4(af[mt], aAddr[mt] + so + kb);
            #pragma unroll
            for (int nt = 0; nt < 4; nt++) ldm_x2(bf[nt], bAddr[nt] + so + kb);
            #pragma unroll
            for (int mt = 0; mt < 4; mt++)
                #pragma unroll
                for (int nt = 0; nt < 4; nt++)
                    mma_f16(acc[mt*4 + nt], af[mt], bf[nt]);
        }
    }

    // epilogue
    #pragma unroll
    for (int mt = 0; mt < 4; mt++) {
        const int row0 = mBase + wm*64 + mt*16 + g;
        #pragma unroll
        for (int nt = 0; nt < 4; nt++) {
            const int col = nBase + wn*32 + nt*8 + 2*q;
            const float* a4 = acc[mt*4 + nt];
            float2 bv = *(const float2*)(bias + col);
            float o0 = a4[0] + bv.x, o1 = a4[1] + bv.y;
            float o2 = a4[2] + bv.x, o3 = a4[3] + bv.y;
            if (RESID) {
                float2 u = *(const float2*)(Rm + (size_t)row0*N + col);
                float2 v = *(const float2*)(Rm + (size_t)(row0+8)*N + col);
                o0 += u.x; o1 += u.y; o2 += v.x; o3 += v.y;
            }
            if (RELU) {
                o0 = fmaxf(o0, 0.f); o1 = fmaxf(o1, 0.f);
                o2 = fmaxf(o2, 0.f); o3 = fmaxf(o3, 0.f);
            }
            if (HOUT) {
                *(uint32_t*)(Ch + (size_t)row0*N + col)     = pack_h2(o0, o1);
                *(uint32_t*)(Ch + (size_t)(row0+8)*N + col) = pack_h2(o2, o3);
            } else {
                *(float2*)(Cf + (size_t)row0*N + col)     = make_float2(o0, o1);
                *(float2*)(Cf + (size_t)(row0+8)*N + col) = make_float2(o2, o3);
            }
        }
    }
}

// ---------------- Flash attention v2 (fp16 mma, causal) — R9 config ----------------
// 64 q-rows x 64 kv-cols tiles; 4 warps (128 thr), warp owns 16 q-rows; occ 2.
#define KP 72                           // pitch (halves) = 144 B
#define ATT_SMEM ((2*64*KP + 2*64*KP + 4*16*KP + 4*16*KP) * 2)

__global__ __launch_bounds__(128, 2)
void attn_kernel(const __half* __restrict__ qkv, __half* __restrict__ out)
{
    extern __shared__ __half sa[];
    __half* Ksm = sa;                    // [2][64][KP]
    __half* Vsm = Ksm + 2*64*KP;         // [2][64][KP]
    __half* Psm = Vsm + 2*64*KP;         // [4][16][KP]
    __half* Qsm = Psm + 4*16*KP;         // [4][16][KP]

    const int tid = threadIdx.x;
    const int w = tid >> 5, lane = tid & 31;
    const int g = lane >> 2, q = lane & 3;
    const int Lt = lane >> 3, Lr = lane & 7;
    const int qi = (gridDim.x - 1) - blockIdx.x;   // longest first
    const int h = blockIdx.y, b = blockIdx.z;
    const int qBase = qi * 64;
    const size_t bT = (size_t)b * TT;

    __half* Pw = Psm + w*16*KP;
    __half* Qw = Qsm + w*16*KP;

    // load Q tile (16 rows x 64 halves)
    {
        const __half* qg = qkv + (bT + qBase + w*16) * 3072 + h*64;
        #pragma unroll
        for (int i = 0; i < 4; i++) {
            int f = lane + i*32;
            int r = f >> 3, c8 = (f & 7) << 3;
            *(uint4*)&Qw[r*KP + c8] = *(const uint4*)(qg + (size_t)r*3072 + c8);
        }
    }
    __syncwarp();

    float m0 = NEG_INF, m1 = NEG_INF, l0 = 0.f, l1 = 0.f;
    float accO[8][4];
    #pragma unroll
    for (int i = 0; i < 8; i++)
        #pragma unroll
        for (int j = 0; j < 4; j++) accO[i][j] = 0.f;

    const int nT = qi + 1;
    const uint32_t skb = s2u(Ksm), svb = s2u(Vsm);
    const uint32_t lmq = s2u(Qw) + (uint32_t)(((((Lt & 1)*8) + Lr)*KP + (Lt >> 1)*8) * 2);
    const uint32_t lmp = s2u(Pw) + (uint32_t)(((((Lt & 1)*8) + Lr)*KP + (Lt >> 1)*8) * 2);
    const uint32_t lmk = skb + (uint32_t)((Lr*KP + (Lt & 1)*8) * 2);   // K frag base
    const uint32_t lmv = svb + (uint32_t)((((Lt & 1)*8 + Lr)*KP) * 2); // V frag base (trans)

    // prologue: kv tile 0 -> stage 0
    {
        const __half* kg = qkv + bT * 3072 + EMB + h*64;
        #pragma unroll
        for (int i = 0; i < 4; i++) {
            int f = tid + i*128;
            int r = f >> 3, c8 = (f & 7) << 3;
            cpa16(skb + (uint32_t)((r*KP + c8)*2), kg + (size_t)r*3072 + c8);
            cpa16(svb + (uint32_t)((r*KP + c8)*2), kg + (size_t)r*3072 + EMB + c8);
        }
        CP_COMMIT();
    }

    #pragma unroll 1
    for (int j = 0; j < nT; ++j) {
        if (j + 1 < nT) {
            const int st = (j + 1) & 1;
            const __half* kg = qkv + (bT + (size_t)(j+1)*64) * 3072 + EMB + h*64;
            #pragma unroll
            for (int i = 0; i < 4; i++) {
                int f = tid + i*128;
                int r = f >> 3, c8 = (f & 7) << 3;
                cpa16(skb + (uint32_t)(((st*64 + r)*KP + c8)*2), kg + (size_t)r*3072 + c8);
                cpa16(svb + (uint32_t)(((st*64 + r)*KP + c8)*2), kg + (size_t)r*3072 + EMB + c8);
            }
            CP_COMMIT();
            CP_WAIT(1);
        } else {
            CP_WAIT(0);
        }
        __syncthreads();

        const uint32_t kst = (uint32_t)((j & 1) * 64 * KP * 2);

        // ---- S = Q @ K^T : 8 n-tiles, 4 k16 steps ----
        float sacc[8][4];
        #pragma unroll
        for (int i = 0; i < 8; i++)
            #pragma unroll
            for (int jj = 0; jj < 4; jj++) sacc[i][jj] = 0.f;

        #pragma unroll
        for (int ks = 0; ks < 4; ks++) {
            const uint32_t kb = (uint32_t)(ks * 32);   // 16 halves
            uint32_t aq[4];
            ldm_x4(aq, lmq + kb);
            uint32_t bf[8][2];
            #pragma unroll
            for (int nt = 0; nt < 8; nt++)
                ldm_x2(bf[nt], lmk + kst + (uint32_t)(nt*8*KP*2) + kb);
            #pragma unroll
            for (int nt = 0; nt < 8; nt++)
                mma_f16(sacc[nt], aq, bf[nt]);
        }

        // scale + causal mask (diag tile only)
        const int r0 = qBase + w*16 + g;
        const int jb = j * 64;
        const bool diag = (j == qi);
        #pragma unroll
        for (int nt = 0; nt < 8; nt++) {
            sacc[nt][0] *= 0.125f; sacc[nt][1] *= 0.125f;
            sacc[nt][2] *= 0.125f; sacc[nt][3] *= 0.125f;
            if (diag) {
                const int c0 = jb + nt*8 + 2*q;
                if (c0     > r0    ) sacc[nt][0] = NEG_INF;
                if (c0 + 1 > r0    ) sacc[nt][1] = NEG_INF;
                if (c0     > r0 + 8) sacc[nt][2] = NEG_INF;
                if (c0 + 1 > r0 + 8) sacc[nt][3] = NEG_INF;
            }
        }

        // ---- online softmax in registers ----
        float ml0 = NEG_INF, ml1 = NEG_INF;
        #pragma unroll
        for (int nt = 0; nt < 8; nt++) {
            ml0 = fmaxf(ml0, fmaxf(sacc[nt][0], sacc[nt][1]));
            ml1 = fmaxf(ml1, fmaxf(sacc[nt][2], sacc[nt][3]));
        }
        ml0 = fmaxf(ml0, __shfl_xor_sync(0xffffffffu, ml0, 1));
        ml0 = fmaxf(ml0, __shfl_xor_sync(0xffffffffu, ml0, 2));
        ml1 = fmaxf(ml1, __shfl_xor_sync(0xffffffffu, ml1, 1));
        ml1 = fmaxf(ml1, __shfl_xor_sync(0xffffffffu, ml1, 2));
        const float mn0 = fmaxf(m0, ml0);
        const float mn1 = fmaxf(m1, ml1);
        const float a0 = __expf(m0 - mn0);
        const float a1 = __expf(m1 - mn1);
        float s0 = 0.f, s1 = 0.f;
        #pragma unroll
        for (int nt = 0; nt < 8; nt++) {
            sacc[nt][0] = __expf(sacc[nt][0] - mn0);
            sacc[nt][1] = __expf(sacc[nt][1] - mn0);
            sacc[nt][2] = __expf(sacc[nt][2] - mn1);
            sacc[nt][3] = __expf(sacc[nt][3] - mn1);
            s0 += sacc[nt][0] + sacc[nt][1];
            s1 += sacc[nt][2] + sacc[nt][3];
        }
        s0 += __shfl_xor_sync(0xffffffffu, s0, 1);
        s0 += __shfl_xor_sync(0xffffffffu, s0, 2);
        s1 += __shfl_xor_sync(0xffffffffu, s1, 1);
        s1 += __shfl_xor_sync(0xffffffffu, s1, 2);
        m0 = mn0; m1 = mn1;
        l0 = l0 * a0 + s0;
        l1 = l1 * a1 + s1;
        #pragma unroll
        for (int dt = 0; dt < 8; dt++) {
            accO[dt][0] *= a0; accO[dt][1] *= a0;
            accO[dt][2] *= a1; accO[dt][3] *= a1;
        }

        // ---- P (half) -> warp-private smem ----
        #pragma unroll
        for (int nt = 0; nt < 8; nt++) {
            const int c = nt*8 + 2*q;
            *(uint32_t*)&Pw[(g    )*KP + c] = pack_h2(sacc[nt][0], sacc[nt][1]);
            *(uint32_t*)&Pw[(g + 8)*KP + c] = pack_h2(sacc[nt][2], sacc[nt][3]);
        }
        __syncwarp();

        // ---- O += P @ V : A = P (ldm x4), B = V (ldm x2 trans) ----
        #pragma unroll
        for (int ks = 0; ks < 4; ks++) {
            const uint32_t kb = (uint32_t)(ks * 32);
            uint32_t af[4];
            ldm_x4(af, lmp + kb);
            const uint32_t vrow = lmv + kst + (uint32_t)(ks*16*KP*2);
            uint32_t bf[8][2];
            #pragma unroll
            for (int dt = 0; dt < 8; dt++)
                ldm_x2_t(bf[dt], vrow + (uint32_t)(dt*8*2));
            #pragma unroll
            for (int dt = 0; dt < 8; dt++)
                mma_f16(accO[dt], af, bf[dt]);
        }
        __syncwarp();
        __syncthreads();
    }

    // ---- finalize: divide by l, write half out [b,t,e] ----
    const float inv0 = 1.f / l0;
    const float inv1 = 1.f / l1;
    const size_t row0 = bT + qBase + w*16 + g;
    #pragma unroll
    for (int dt = 0; dt < 8; dt++) {
        const int c = h*64 + dt*8 + 2*q;
        *(uint32_t*)(out + row0*EMB + c)       = pack_h2(accO[dt][0]*inv0, accO[dt][1]*inv0);
        *(uint32_t*)(out + (row0 + 8)*EMB + c) = pack_h2(accO[dt][2]*inv1, accO[dt][3]*inv1);
    }
}

// ---------------- LayerNorm over last dim (1024) ----------------
__global__ __launch_bounds__(256)
void ln_kernel(const float* __restrict__ in, const float* __restrict__ g,
               const float* __restrict__ bb, float* __restrict__ out,
               __half* __restrict__ outh)
{
    const int row = blockIdx.x, tid = threadIdx.x;
    const float* rp = in + (size_t)row * EMB;
    float4 v = *(const float4*)(rp + tid*4);
    float s  = v.x + v.y + v.z + v.w;
    float sq = v.x*v.x + v.y*v.y + v.z*v.z + v.w*v.w;
    #pragma unroll
    for (int o = 16; o > 0; o >>= 1) {
        s  += __shfl_xor_sync(0xffffffffu, s,  o);
        sq += __shfl_xor_sync(0xffffffffu, sq, o);
    }
    __shared__ float ws[8], wq[8], stat[2];
    const int w = tid >> 5;
    if ((tid & 31) == 0) { ws[w] = s; wq[w] = sq; }
    __syncthreads();
    if (tid == 0) {
        float ts = 0.f, tq = 0.f;
        #pragma unroll
        for (int i = 0; i < 8; i++) { ts += ws[i]; tq += wq[i]; }
        float mean = ts * (1.f/EMB);
        float var  = tq * (1.f/EMB) - mean*mean;
        stat[0] = mean;
        stat[1] = rsqrtf(var + 1e-5f);
    }
    __syncthreads();
    const float mean = stat[0], rs = stat[1];
    float4 gv = *(const float4*)(g  + tid*4);
    float4 bv = *(const float4*)(bb + tid*4);
    float4 o;
    o.x = (v.x - mean)*rs*gv.x + bv.x;
    o.y = (v.y - mean)*rs*gv.y + bv.y;
    o.z = (v.z - mean)*rs*gv.z + bv.z;
    o.w = (v.w - mean)*rs*gv.w + bv.w;
    *(float4*)(out + (size_t)row*EMB + tid*4) = o;
    if (outh) {
        *(uint2*)(outh + (size_t)row*EMB + tid*4) =
            make_uint2(pack_h2(o.x, o.y), pack_h2(o.z, o.w));
    }
}

// ---------------- launch ----------------
extern "C" void kernel_launch(void* const* d_in, const int* in_sizes, int n_in,
                              void* d_out, int out_size)
{
    const float* x   = (const float*)d_in[0];
    const float* wat = (const float*)d_in[1];
    const float* bat = (const float*)d_in[2];
    const float* wpr = (const float*)d_in[3];
    const float* bpr = (const float*)d_in[4];
    const float* l1g = (const float*)d_in[5];
    const float* l1b = (const float*)d_in[6];
    const float* wf1 = (const float*)d_in[7];
    const float* bf1 = (const float*)d_in[8];
    const float* wf2 = (const float*)d_in[9];
    const float* bf2 = (const float*)d_in[10];
    const float* l2g = (const float*)d_in[11];
    const float* l2b = (const float*)d_in[12];

    static __half *xh = nullptr, *qkvh, *atth, *x1h, *ffh, *watT, *wprT, *wf1T, *wf2T;
    static float *res1, *x1f, *res2;
    static cudaStream_t side = nullptr;
    static cudaEvent_t evF, evJ1, evJ2;
    if (!xh) {
        cudaGetSymbolAddress((void**)&xh,   g_xh);
        cudaGetSymbolAddress((void**)&qkvh, g_qkvh);
        cudaGetSymbolAddress((void**)&atth, g_atth);
        cudaGetSymbolAddress((void**)&res1, g_res1);
        cudaGetSymbolAddress((void**)&x1f,  g_x1f);
        cudaGetSymbolAddress((void**)&x1h,  g_x1h);
        cudaGetSymbolAddress((void**)&ffh,  g_ffh);
        cudaGetSymbolAddress((void**)&res2, g_res2);
        cudaGetSymbolAddress((void**)&watT, g_watT);
        cudaGetSymbolAddress((void**)&wprT, g_wprT);
        cudaGetSymbolAddress((void**)&wf1T, g_wf1T);
        cudaGetSymbolAddress((void**)&wf2T, g_wf2T);
        cudaFuncSetAttribute(attn_kernel, cudaFuncAttributeMaxDynamicSharedMemorySize, ATT_SMEM);
        cudaFuncSetAttribute(gemm_mma<false,false,true>, cudaFuncAttributeMaxDynamicSharedMemorySize, GSMEM);
        cudaFuncSetAttribute(gemm_mma<false,true,false>, cudaFuncAttributeMaxDynamicSharedMemorySize, GSMEM);
        cudaFuncSetAttribute(gemm_mma<true,false,true>,  cudaFuncAttributeMaxDynamicSharedMemorySize, GSMEM);
        cudaStreamCreateWithFlags(&side, cudaStreamNonBlocking);
        cudaEventCreateWithFlags(&evF,  cudaEventDisableTiming);
        cudaEventCreateWithFlags(&evJ1, cudaEventDisableTiming);
        cudaEventCreateWithFlags(&evJ2, cudaEventDisableTiming);
    }

    // ---- fork: weight transposes run on side stream, overlapping main work ----
    cudaEventRecord(evF, 0);
    cudaStreamWaitEvent(side, evF, 0);
    // side: wat first (needed by QKV), then the rest (needed only from proj onward)
    transpose_cvt<<<dim3(3*EMB/32, EMB/32), dim3(32,8), 0, side>>>(wat, watT, EMB, 3*EMB);
    cudaEventRecord(evJ1, side);
    transpose_cvt<<<dim3(EMB/32,   EMB/32), dim3(32,8), 0, side>>>(wpr, wprT, EMB, EMB);
    transpose_cvt<<<dim3(DFF/32,   EMB/32), dim3(32,8), 0, side>>>(wf1, wf1T, EMB, DFF);
    transpose_cvt<<<dim3(EMB/32,   DFF/32), dim3(32,8), 0, side>>>(wf2, wf2T, DFF, EMB);
    cudaEventRecord(evJ2, side);

    // main: x -> half (parallel with wat transpose)
    cvt_half<<<MR*EMB/1024, 256>>>((const float4*)x, (uint2*)xh);

    // join 1: QKV needs watT
    cudaStreamWaitEvent(0, evJ1, 0);
    // 1. QKV projection -> half
    gemm_mma<false,false,true><<<dim3(3*EMB/128, MR/128), 256, GSMEM>>>(xh, watT, bat, nullptr, nullptr, qkvh, 3*EMB, EMB);
    // 2. causal flash attention -> half   (overlaps wpr/wf1/wf2 transposes)
    attn_kernel<<<dim3(TT/64, NH, BB), 128, ATT_SMEM>>>(qkvh, atth);

    // join 2: proj needs wprT (wf1T/wf2T come even later)
    cudaStreamWaitEvent(0, evJ2, 0);
    // 3. output proj + residual(x) -> fp32
    gemm_mma<false,true,false><<<dim3(EMB/128, MR/128), 256, GSMEM>>>(atth, wprT, bpr, x, res1, nullptr, EMB, EMB);
    // 4. LN1 -> x1f (fp32) + x1h (half)
    ln_kernel<<<MR, 256>>>(res1, l1g, l1b, x1f, x1h);
    // 5. FF1 + ReLU -> half
    gemm_mma<true,false,true><<<dim3(DFF/128, MR/128), 256, GSMEM>>>(x1h, wf1T, bf1, nullptr, nullptr, ffh, DFF, EMB);
    // 6. FF2 + residual(x1f) -> fp32
    gemm_mma<false,true,false><<<dim3(EMB/128, MR/128), 256, GSMEM>>>(ffh, wf2T, bf2, x1f, res2, nullptr, EMB, DFF);
    // 7. LN2 -> out
    ln_kernel<<<MR, 256>>>(res2, l2g, l2b, (float*)d_out, nullptr);
}